// round 7
// baseline (speedup 1.0000x reference)
#include <cuda_runtime.h>
#include <math.h>

#define PATCH 7
#define PP 49

#define BM 32
#define BN 64
#define BK 32
#define NSPLIT 4
#define AS_STRIDE (BM + 4)   // 36

// Scratch: partial-product buffers, ping-pong per layer.
// partA/partB each hold NSPLIT x (1024*256) floats.
__device__ float g_partA[1 << 20];
__device__ float g_partB[1 << 20];

// ---------------------------------------------------------------------------
// Split-K partial GEMM with fused input-combine.
// Computes Cpart[z] = Ain[:, z*Ks:(z+1)*Ks] @ W[z*Ks:(z+1)*Ks, :]
// where Ain = FUSED ? relu(sum_s Apart[s] + abias) : A.
// BM=32, BN=64, BK=32, 128 threads, 4x4 per thread, k-major smem A,
// double-buffered smem with register prefetch.
// ---------------------------------------------------------------------------
template <bool FUSED>
__global__ void __launch_bounds__(128)
gemm_partial_kernel(const float* __restrict__ A,      // used if !FUSED
                    const float* __restrict__ Apart,  // used if FUSED (NSPLIT bufs)
                    const float* __restrict__ abias,  // used if FUSED
                    const float* __restrict__ W,
                    float* __restrict__ Cpart, int M, int N, int K) {
    __shared__ float As[2][BK][AS_STRIDE];
    __shared__ float Bs[2][BK][BN];

    const int tid = threadIdx.x;
    const int block_m = blockIdx.y * BM;
    const int block_n = blockIdx.x * BN;
    const int Ks = K / NSPLIT;                 // 64
    const int k0s = blockIdx.z * Ks;
    const size_t pstride = (size_t)M * K;      // partial-buffer stride (A side)

    // A-tile load: row = tid&31, kg = tid>>5 (0..3) -> 8 consecutive k
    const int a_row = tid & 31;
    const int a_kg  = tid >> 5;
    const size_t a_off0 = (size_t)(block_m + a_row) * K + k0s + a_kg * 8;

    // B-tile load: kr = tid>>4 (0..7), rows kr+{0,8,16,24}, c=(tid&15)*4
    const int b_kr = tid >> 4;
    const int b_c  = (tid & 15) * 4;
    const size_t w_base = (size_t)(k0s + b_kr) * N + block_n + b_c;
    const size_t w_step = (size_t)8 * N;

    // Compute mapping
    const int tx = tid & 15;
    const int ty = tid >> 4;

    float4 aR0, aR1;
    float4 bR[4];

    // fused A-element producer: 8 floats at a_off0 + koff (2 float4)
    auto load_a = [&](size_t koff, float4& r0, float4& r1) {
        if (!FUSED) {
            r0 = *reinterpret_cast<const float4*>(&A[a_off0 + koff]);
            r1 = *reinterpret_cast<const float4*>(&A[a_off0 + koff + 4]);
        } else {
            const size_t o = a_off0 + koff;
            float4 s0 = *reinterpret_cast<const float4*>(&Apart[o]);
            float4 s1 = *reinterpret_cast<const float4*>(&Apart[o + 4]);
#pragma unroll
            for (int s = 1; s < NSPLIT; s++) {
                float4 t0 = *reinterpret_cast<const float4*>(&Apart[s * pstride + o]);
                float4 t1 = *reinterpret_cast<const float4*>(&Apart[s * pstride + o + 4]);
                s0.x += t0.x; s0.y += t0.y; s0.z += t0.z; s0.w += t0.w;
                s1.x += t1.x; s1.y += t1.y; s1.z += t1.z; s1.w += t1.w;
            }
            const int c0 = k0s + a_kg * 8 + (int)koff;   // column of first element
            float4 bb0 = *reinterpret_cast<const float4*>(&abias[c0]);
            float4 bb1 = *reinterpret_cast<const float4*>(&abias[c0 + 4]);
            r0.x = fmaxf(s0.x + bb0.x, 0.f);
            r0.y = fmaxf(s0.y + bb0.y, 0.f);
            r0.z = fmaxf(s0.z + bb0.z, 0.f);
            r0.w = fmaxf(s0.w + bb0.w, 0.f);
            r1.x = fmaxf(s1.x + bb1.x, 0.f);
            r1.y = fmaxf(s1.y + bb1.y, 0.f);
            r1.z = fmaxf(s1.z + bb1.z, 0.f);
            r1.w = fmaxf(s1.w + bb1.w, 0.f);
        }
    };

    // ---- tile 0 ----
    load_a(0, aR0, aR1);
#pragma unroll
    for (int i = 0; i < 4; i++)
        bR[i] = *reinterpret_cast<const float4*>(&W[w_base + i * w_step]);
    {
        const float* av0 = &aR0.x;
        const float* av1 = &aR1.x;
#pragma unroll
        for (int j = 0; j < 4; j++) As[0][a_kg * 8 + j][a_row] = av0[j];
#pragma unroll
        for (int j = 0; j < 4; j++) As[0][a_kg * 8 + 4 + j][a_row] = av1[j];
#pragma unroll
        for (int i = 0; i < 4; i++)
            *reinterpret_cast<float4*>(&Bs[0][b_kr + i * 8][b_c]) = bR[i];
    }
    __syncthreads();

    float acc[4][4];
#pragma unroll
    for (int i = 0; i < 4; i++)
#pragma unroll
        for (int j = 0; j < 4; j++) acc[i][j] = 0.f;

    const int nt = Ks / BK;                    // 2
    int cur = 0;

    for (int t = 0; t < nt; t++) {
        if (t + 1 < nt) {
            const size_t koff = (size_t)(t + 1) * BK;
            load_a(koff, aR0, aR1);
#pragma unroll
            for (int i = 0; i < 4; i++)
                bR[i] = *reinterpret_cast<const float4*>(&W[w_base + koff * N + i * w_step]);
        }

#pragma unroll
        for (int kk = 0; kk < BK; kk++) {
            float4 a4 = *reinterpret_cast<const float4*>(&As[cur][kk][ty * 4]);
            float4 b4 = *reinterpret_cast<const float4*>(&Bs[cur][kk][tx * 4]);
            const float a[4] = {a4.x, a4.y, a4.z, a4.w};
            const float b[4] = {b4.x, b4.y, b4.z, b4.w};
#pragma unroll
            for (int i = 0; i < 4; i++)
#pragma unroll
                for (int j = 0; j < 4; j++)
                    acc[i][j] = fmaf(a[i], b[j], acc[i][j]);
        }

        if (t + 1 < nt) {
            const int nxt = cur ^ 1;
            const float* av0 = &aR0.x;
            const float* av1 = &aR1.x;
#pragma unroll
            for (int j = 0; j < 4; j++) As[nxt][a_kg * 8 + j][a_row] = av0[j];
#pragma unroll
            for (int j = 0; j < 4; j++) As[nxt][a_kg * 8 + 4 + j][a_row] = av1[j];
#pragma unroll
            for (int i = 0; i < 4; i++)
                *reinterpret_cast<float4*>(&Bs[nxt][b_kr + i * 8][b_c]) = bR[i];
        }
        __syncthreads();
        cur ^= 1;
    }

    // store raw partials for this split
    float* out = Cpart + (size_t)blockIdx.z * M * N;
    const int col = block_n + tx * 4;
#pragma unroll
    for (int i = 0; i < 4; i++) {
        const int row = block_m + ty * 4 + i;
        float4 v = make_float4(acc[i][0], acc[i][1], acc[i][2], acc[i][3]);
        *reinterpret_cast<float4*>(&out[(size_t)row * N + col]) = v;
    }
}

// ---------------------------------------------------------------------------
// Patch gather + dot + indices, with fused final combine:
// qe[n,d] = sum_s qpart[s][n,d] + b3[d]   (no relu on final layer)
// One block (256 threads) per query.
// Output layout in d_out (float32):
//   [0, N*49)        logits (n, py, px)
//   [N*49, N*49*5)   indices as float (n, py, px, {b,y,x,q})
// ---------------------------------------------------------------------------
__global__ void __launch_bounds__(256)
patch_kernel(const float* __restrict__ fm, const float* __restrict__ qpart,
             const float* __restrict__ b3,
             const float* __restrict__ qpos, const int* __restrict__ shapes,
             float* __restrict__ out, int N, int Q, int D) {
    __shared__ float sq[256];
    const int n = blockIdx.x;
    if (n >= N) return;

    const int b = n / Q;
    const int q = n - b * Q;
    const int Hb = shapes[2 * b + 0];
    const int Wb = shapes[2 * b + 1];

    const float posx = qpos[2 * n + 0];
    const float posy = qpos[2 * n + 1];
    const int cy = (int)(posy * (float)Hb);
    const int cx = (int)(posx * (float)Wb);

    const size_t pstride = (size_t)N * D;
    for (int d = threadIdx.x; d < D; d += blockDim.x) {
        const size_t o = (size_t)n * D + d;
        float v = qpart[o] + qpart[o + pstride] + qpart[o + 2 * pstride] +
                  qpart[o + 3 * pstride] + b3[d];
        sq[d] = v;
    }
    __syncthreads();

    const int warp = threadIdx.x >> 5;
    const int lane = threadIdx.x & 31;
    const float4* sq4 = reinterpret_cast<const float4*>(sq);
    const float4 q0 = sq4[lane];
    const float4 q1 = sq4[lane + 32];

    float* out_logits = out;
    float* out_idx = out + (size_t)N * PP;

    for (int p = warp; p < PP; p += 8) {
        const int dy = p / PATCH - PATCH / 2;
        const int dx = p % PATCH - PATCH / 2;
        int y = cy + dy;
        int x = cx + dx;
        y = min(max(y, 0), Hb - 1);
        x = min(max(x, 0), Wb - 1);

        const size_t row_off = (((size_t)b * Hb + y) * Wb + x) * (size_t)D;
        const float4* row = reinterpret_cast<const float4*>(fm + row_off);

        const float4 f0 = row[lane];
        const float4 f1 = row[lane + 32];

        float s = f0.x * q0.x + f0.y * q0.y + f0.z * q0.z + f0.w * q0.w;
        s = fmaf(f1.x, q1.x, s);
        s = fmaf(f1.y, q1.y, s);
        s = fmaf(f1.z, q1.z, s);
        s = fmaf(f1.w, q1.w, s);

#pragma unroll
        for (int off = 16; off; off >>= 1)
            s += __shfl_xor_sync(0xFFFFFFFFu, s, off);

        if (lane == 0) {
            out_logits[(size_t)n * PP + p] = s;
            float4 iv = make_float4((float)b, (float)y, (float)x, (float)q);
            *reinterpret_cast<float4*>(&out_idx[((size_t)n * PP + p) * 4]) = iv;
        }
    }
}

extern "C" void kernel_launch(void* const* d_in, const int* in_sizes, int n_in,
                              void* d_out, int out_size) {
    const float* fm      = (const float*)d_in[0];
    const float* queries = (const float*)d_in[1];
    const float* qpos    = (const float*)d_in[2];
    const int*   shapes  = (const int*)d_in[4];
    const float* W0 = (const float*)d_in[5];
    const float* b0 = (const float*)d_in[6];
    const float* W1 = (const float*)d_in[7];
    const float* b1 = (const float*)d_in[8];
    const float* W2 = (const float*)d_in[9];
    const float* b2 = (const float*)d_in[10];
    const float* W3 = (const float*)d_in[11];
    const float* b3 = (const float*)d_in[12];

    const int B = in_sizes[3];               // query_batch_offsets length
    const int D = in_sizes[6];               // bias length
    const int N = in_sizes[1] / D;           // total queries
    const int Q = N / B;

    float* partA;
    float* partB;
    cudaGetSymbolAddress((void**)&partA, g_partA);
    cudaGetSymbolAddress((void**)&partB, g_partB);

    dim3 gblock(128);
    dim3 ggrid(D / BN, N / BM, NSPLIT);      // (4, 32, 4) = 512 blocks

    // layer 0: reads queries directly, writes partials A
    gemm_partial_kernel<false><<<ggrid, gblock>>>(queries, nullptr, nullptr, W0, partA, N, D, D);
    // layer 1: fuses relu(sum partA + b0) as input, writes partials B
    gemm_partial_kernel<true ><<<ggrid, gblock>>>(nullptr, partA, b0, W1, partB, N, D, D);
    // layer 2
    gemm_partial_kernel<true ><<<ggrid, gblock>>>(nullptr, partB, b1, W2, partA, N, D, D);
    // layer 3
    gemm_partial_kernel<true ><<<ggrid, gblock>>>(nullptr, partA, b2, W3, partB, N, D, D);

    // patch: fuses final combine (sum partB + b3, no relu)
    patch_kernel<<<N, 256>>>(fm, partB, b3, qpos, shapes, (float*)d_out, N, Q, D);
}